// round 8
// baseline (speedup 1.0000x reference)
#include <cuda_runtime.h>
#include <cuda_bf16.h>

#define EPS     1e-5f
#define THREADS 256
#define TILE_M  128
#define NPTS    (64 * 1024)
#define NBLK    (NPTS / TILE_M)   // 512 CTAs

// ---- pre-folded weights (bf16 hi/lo, fragment layout) + biases in device globals ----
// wbuf: W1H@0(4096) W1L@4096 W2H@8192(8192) W2L@16384 W3H@24576 W3L@32768 -> 40960 B
__device__ __align__(16) char  wbuf[40960];
__device__ __align__(16) float bbuf[192];

// ---- SMEM byte layout ----
#define OFF_BIAS 0                       // 192 f32 (pad to 1024)
#define OFF_W    1024                    // 40960 B weight block (same internal offsets as wbuf)
#define OFF_BUF  (OFF_W + 40960)         // x staging (128x36 f32) / out transpose (64x132 f32)
#define BUF_STRIDE 132
#define X_STRIDE   36
#define SMEM_BYTES (OFF_BUF + 64 * BUF_STRIDE * 4)   // 75776 B -> 2 CTAs/SM

typedef unsigned long long ull;

// ---- packed fp32x2 helpers ----
__device__ __forceinline__ ull fma2(ull a, ull b, ull c) {
    ull d; asm("fma.rn.f32x2 %0,%1,%2,%3;" : "=l"(d) : "l"(a), "l"(b), "l"(c)); return d;
}
__device__ __forceinline__ ull add2(ull a, ull b) {
    ull d; asm("add.rn.f32x2 %0,%1,%2;" : "=l"(d) : "l"(a), "l"(b)); return d;
}
__device__ __forceinline__ ull mul2(ull a, ull b) {
    ull d; asm("mul.rn.f32x2 %0,%1,%2;" : "=l"(d) : "l"(a), "l"(b)); return d;
}
__device__ __forceinline__ void unpk(ull v, float& lo, float& hi) {
    asm("mov.b64 {%0,%1}, %2;" : "=f"(lo), "=f"(hi) : "l"(v));
}
__device__ __forceinline__ ull pk2(float lo, float hi) {
    ull v; asm("mov.b64 %0, {%1,%2};" : "=l"(v) : "f"(lo), "f"(hi)); return v;
}
__device__ __forceinline__ ull pkc(float c) {
    unsigned u = __float_as_uint(c); return ((ull)u << 32) | (ull)u;
}
__device__ __forceinline__ float frcp(float x) {
    float r; asm("rcp.approx.f32 %0,%1;" : "=f"(r) : "f"(x)); return r;
}
__device__ __forceinline__ float fex2(float x) {
    float r; asm("ex2.approx.f32 %0,%1;" : "=f"(r) : "f"(x)); return r;
}

// Branch-free exact-class GELU on a packed fp32x2 pair (A&S 7.1.26, |err|<=1.5e-7 abs).
__device__ __forceinline__ ull gelu2(ull s) {
    const ull C_ISQ2 = pkc(0.70710678118654752f);
    ull a = mul2(s & 0x7FFFFFFF7FFFFFFFULL, C_ISQ2);
    ull d = fma2(a, pkc(0.3275911f), pkc(1.0f));
    float dl, dh; unpk(d, dl, dh);
    ull u = pk2(frcp(dl), frcp(dh));
    ull p = fma2(u, pkc(1.061405429f), pkc(-1.453152027f));
    p = fma2(u, p, pkc(1.421413741f));
    p = fma2(u, p, pkc(-0.284496736f));
    p = fma2(u, p, pkc(0.254829592f));
    p = mul2(p, u);
    ull m = mul2(mul2(a, a), pkc(-1.4426950408889634f));
    float ml, mh; unpk(m, ml, mh);
    ull e = pk2(fex2(ml), fex2(mh));
    ull pe = mul2(p, e);
    ull hm = mul2(a, C_ISQ2);
    ull r = fma2(pe ^ 0x8000000080000000ULL, hm, hm);
    return fma2(s, pkc(0.5f), r);
}

// packed f32 pair -> (bf16x2 hi, bf16x2 lo-residual)
__device__ __forceinline__ void splitpair(ull v, unsigned& hb, unsigned& lb) {
    float f0, f1; unpk(v, f0, f1);
    unsigned h;
    asm("cvt.rn.bf16x2.f32 %0, %1, %2;" : "=r"(h) : "f"(f1), "f"(f0));
    float a0 = __uint_as_float(h << 16);
    float a1 = __uint_as_float(h & 0xFFFF0000u);
    float r0 = f0 - a0, r1 = f1 - a1;
    unsigned l;
    asm("cvt.rn.bf16x2.f32 %0, %1, %2;" : "=r"(l) : "f"(r1), "f"(r0));
    hb = h; lb = l;
}

// D += A(m16k16 bf16, row) @ B(k16n8 bf16, col); fp32 accum. Baseline PTX (sm_80+).
__device__ __forceinline__ void mma16816(float d[4], const unsigned a[4],
                                         unsigned b0, unsigned b1) {
    asm volatile(
        "mma.sync.aligned.m16n8k16.row.col.f32.bf16.bf16.f32 "
        "{%0,%1,%2,%3},{%4,%5,%6,%7},{%8,%9},{%0,%1,%2,%3};"
        : "+f"(d[0]), "+f"(d[1]), "+f"(d[2]), "+f"(d[3])
        : "r"(a[0]), "r"(a[1]), "r"(a[2]), "r"(a[3]), "r"(b0), "r"(b1));
}

// Fragment-layout offset: 8B unit(o,t,p) holds bf16 {k=16t+2p,+1,+8,+9} for output o;
// t XOR-swizzled so the 16-lane LDS.64 phase is conflict-free.
template<int KT>
__device__ __forceinline__ int woff(int o, int k) {
    int t = k >> 4, kk = k & 15, pp = (kk & 7) >> 1, half = kk >> 3;
    int ts = t ^ (o & (KT - 1));
    return ((o * KT + ts) * 4 + pp) * 8 + half * 4 + (k & 1) * 2;
}

// ---- one-shot fold kernel: BN-fold + bf16 hi/lo split into fragment layout ----
__global__ void fold_kernel(
    const float* __restrict__ W1, const float* __restrict__ g1, const float* __restrict__ b1,
    const float* __restrict__ m1, const float* __restrict__ v1,
    const float* __restrict__ W2, const float* __restrict__ g2, const float* __restrict__ b2,
    const float* __restrict__ m2, const float* __restrict__ v2,
    const float* __restrict__ W3, const float* __restrict__ g3, const float* __restrict__ b3,
    const float* __restrict__ m3, const float* __restrict__ v3)
{
    int i = blockIdx.x * blockDim.x + threadIdx.x;
    if (i < 2048) {                               // W1 [64x32]
        int o = i >> 5, k = i & 31;
        float w = W1[i] * (g1[o] * rsqrtf(v1[o] + EPS));
        __nv_bfloat16 hi = __float2bfloat16(w);
        int off = woff<2>(o, k);
        *(__nv_bfloat16*)(wbuf + off)        = hi;
        *(__nv_bfloat16*)(wbuf + 4096 + off) = __float2bfloat16(w - __bfloat162float(hi));
    } else if (i < 2048 + 4096) {                 // W2 [64x64]
        int j = i - 2048, o = j >> 6, k = j & 63;
        float w = W2[j] * (g2[o] * rsqrtf(v2[o] + EPS));
        __nv_bfloat16 hi = __float2bfloat16(w);
        int off = woff<4>(o, k);
        *(__nv_bfloat16*)(wbuf + 8192 + off)  = hi;
        *(__nv_bfloat16*)(wbuf + 16384 + off) = __float2bfloat16(w - __bfloat162float(hi));
    } else if (i < 2048 + 8192) {                 // W3 [64x64]
        int j = i - 6144, o = j >> 6, k = j & 63;
        float w = W3[j] * (g3[o] * rsqrtf(v3[o] + EPS));
        __nv_bfloat16 hi = __float2bfloat16(w);
        int off = woff<4>(o, k);
        *(__nv_bfloat16*)(wbuf + 24576 + off) = hi;
        *(__nv_bfloat16*)(wbuf + 32768 + off) = __float2bfloat16(w - __bfloat162float(hi));
    }
    if (i < 64) {
        bbuf[i]       = b1[i] - m1[i] * (g1[i] * rsqrtf(v1[i] + EPS));
        bbuf[64 + i]  = b2[i] - m2[i] * (g2[i] * rsqrtf(v2[i] + EPS));
        bbuf[128 + i] = b3[i] - m3[i] * (g3[i] * rsqrtf(v3[i] + EPS));
    }
}

// One GEMM stage (per warp, one 16-row m-tile): D[8][4] = (Ah+Al)@(Wh+Wl)^T, dropping lo*lo.
template<int KT>
__device__ __forceinline__ void run_stage(const char* whi, const char* wlo,
                                          unsigned Ah[4][4], unsigned Al[4][4],
                                          float D[8][4], int g, int p) {
    #pragma unroll
    for (int j = 0; j < 8; ++j)
        #pragma unroll
        for (int r = 0; r < 4; ++r) D[j][r] = 0.f;

    #pragma unroll
    for (int j = 0; j < 8; ++j) {
        int o = 8 * j + g;
        #pragma unroll
        for (int t = 0; t < KT; ++t) {
            int ts = t ^ (o & (KT - 1));
            int unit = (o * KT + ts) * 4 + p;
            ull wh = *(const ull*)(whi + unit * 8);
            ull wl = *(const ull*)(wlo + unit * 8);
            unsigned bh0 = (unsigned)wh, bh1 = (unsigned)(wh >> 32);
            unsigned bl0 = (unsigned)wl, bl1 = (unsigned)(wl >> 32);
            mma16816(D[j], Ah[t], bh0, bh1);   // hi*hi
            mma16816(D[j], Ah[t], bl0, bl1);   // hi*lo
            mma16816(D[j], Al[t], bh0, bh1);   // lo*hi
        }
    }
}

// bias + gelu + re-split into next stage's A fragments (pure per-thread register work)
__device__ __forceinline__ void epilogue_mid(float D[8][4], const float* bias,
                                             unsigned Ah[4][4], unsigned Al[4][4], int p) {
    #pragma unroll
    for (int j = 0; j < 8; ++j) {
        ull bp = *(const ull*)(bias + 8 * j + 2 * p);
        int t = j >> 1;
        int rb = (j & 1) ? 2 : 0;
        ull v0 = gelu2(add2(pk2(D[j][0], D[j][1]), bp));
        ull v1 = gelu2(add2(pk2(D[j][2], D[j][3]), bp));
        splitpair(v0, Ah[t][rb],     Al[t][rb]);
        splitpair(v1, Ah[t][rb + 1], Al[t][rb + 1]);
    }
}

__global__ void __launch_bounds__(THREADS, 2) mlp_mma_kernel(
    const float* __restrict__ x, float* __restrict__ out)
{
    extern __shared__ char smem[];
    const int tid = threadIdx.x;

    // ---- prologue: flat copy of pre-folded weights + biases into SMEM ----
    {
        const uint4* src = (const uint4*)wbuf;
        uint4* dst = (uint4*)(smem + OFF_W);
        #pragma unroll
        for (int i = 0; i < 10; ++i) dst[tid + i * THREADS] = src[tid + i * THREADS];
        if (tid < 48) ((uint4*)(smem + OFF_BIAS))[tid] = ((const uint4*)bbuf)[tid];
    }

    // ---- stage x tile into SMEM (coalesced), padded stride ----
    float* sx = (float*)(smem + OFF_BUF);
    const size_t xbase = (size_t)blockIdx.x * TILE_M * 32;
    for (int i = tid; i < TILE_M * 32; i += THREADS) {
        int r = i >> 5, k = i & 31;
        sx[r * X_STRIDE + k] = x[xbase + i];
    }
    __syncthreads();

    const float* sbias = (const float*)(smem + OFF_BIAS);
    const int lane = tid & 31, wid = tid >> 5;   // warp = one 16-row m-tile
    const int g = lane >> 2, p = lane & 3;

    // ---- build stage-1 A fragments from x (K=32: t=0,1) ----
    unsigned Ah[4][4], Al[4][4];
    {
        int r0 = wid * 16 + g;
        #pragma unroll
        for (int t = 0; t < 2; ++t) {
            int c0 = p * 2 + t * 16;
            splitpair(*(const ull*)(sx + r0 * X_STRIDE + c0),           Ah[t][0], Al[t][0]);
            splitpair(*(const ull*)(sx + (r0 + 8) * X_STRIDE + c0),     Ah[t][1], Al[t][1]);
            splitpair(*(const ull*)(sx + r0 * X_STRIDE + c0 + 8),       Ah[t][2], Al[t][2]);
            splitpair(*(const ull*)(sx + (r0 + 8) * X_STRIDE + c0 + 8), Ah[t][3], Al[t][3]);
        }
    }
    __syncthreads();   // x reads done before OFF_BUF is reused as transpose buffer

    float D[8][4];

    run_stage<2>(smem + OFF_W,         smem + OFF_W + 4096,  Ah, Al, D, g, p);
    epilogue_mid(D, sbias, Ah, Al, p);

    run_stage<4>(smem + OFF_W + 8192,  smem + OFF_W + 16384, Ah, Al, D, g, p);
    epilogue_mid(D, sbias + 64, Ah, Al, p);

    run_stage<4>(smem + OFF_W + 24576, smem + OFF_W + 32768, Ah, Al, D, g, p);

    // ---- final: bias + gelu -> SMEM transpose (conflict-free) -> coalesced STG ----
    float* buf = (float*)(smem + OFF_BUF);
    #pragma unroll
    for (int j = 0; j < 8; ++j) {
        ull bp = *(const ull*)(sbias + 128 + 8 * j + 2 * p);
        int o0 = 8 * j + 2 * p;
        int r0 = wid * 16 + g;
        ull v0 = gelu2(add2(pk2(D[j][0], D[j][1]), bp));
        ull v1 = gelu2(add2(pk2(D[j][2], D[j][3]), bp));
        float f0, f1;
        unpk(v0, f0, f1);
        buf[o0 * BUF_STRIDE + r0]       = f0;
        buf[(o0 + 1) * BUF_STRIDE + r0] = f1;
        unpk(v1, f0, f1);
        buf[o0 * BUF_STRIDE + r0 + 8]       = f0;
        buf[(o0 + 1) * BUF_STRIDE + r0 + 8] = f1;
    }
    __syncthreads();

    // 256 threads: lower half stores o=0..31, upper half o=32..63 (for its 128 points)
    const int pbase = blockIdx.x * TILE_M;
    const int pt = tid & 127;
    const int ob = (tid >> 7) * 32;
    const int pp = pbase + pt;
    float* outp = out + (size_t)(pp >> 10) * 65536 + (pp & 1023) + (size_t)ob * 1024;
    #pragma unroll 8
    for (int o = 0; o < 32; ++o)
        outp[(size_t)o * 1024] = buf[(ob + o) * BUF_STRIDE + pt];
}

extern "C" void kernel_launch(void* const* d_in, const int* in_sizes, int n_in,
                              void* d_out, int out_size)
{
    const float* x  = (const float*)d_in[0];
    const float* W1 = (const float*)d_in[1];
    const float* g1 = (const float*)d_in[2];
    const float* b1 = (const float*)d_in[3];
    const float* m1 = (const float*)d_in[4];
    const float* v1 = (const float*)d_in[5];
    const float* W2 = (const float*)d_in[6];
    const float* g2 = (const float*)d_in[7];
    const float* b2 = (const float*)d_in[8];
    const float* m2 = (const float*)d_in[9];
    const float* v2 = (const float*)d_in[10];
    const float* W3 = (const float*)d_in[11];
    const float* g3 = (const float*)d_in[12];
    const float* b3 = (const float*)d_in[13];
    const float* m3 = (const float*)d_in[14];
    const float* v3 = (const float*)d_in[15];
    float* out = (float*)d_out;

    fold_kernel<<<40, 256>>>(W1, g1, b1, m1, v1, W2, g2, b2, m2, v2, W3, g3, b3, m3, v3);

    cudaFuncSetAttribute(mlp_mma_kernel,
                         cudaFuncAttributeMaxDynamicSharedMemorySize, SMEM_BYTES);
    mlp_mma_kernel<<<NBLK, THREADS, SMEM_BYTES>>>(x, out);
}

// round 9
// speedup vs baseline: 1.3265x; 1.3265x over previous
#include <cuda_runtime.h>
#include <cuda_bf16.h>

#define EPS     1e-5f
#define THREADS 256
#define TILE_M  128
#define NPTS    (64 * 1024)
#define NBLK    (NPTS / TILE_M)   // 512 CTAs

// ---- pre-folded weights: bf16 hi|lo interleaved per 16B unit, fragment layout ----
// W1 @0 (8192B, KT=2), W2 @8192 (16384B, KT=4), W3 @24576 (16384B, KT=4)
__device__ __align__(16) char  wbuf[40960];
__device__ __align__(16) float bbuf[192];

typedef unsigned long long ull;

// ---- packed fp32x2 helpers ----
__device__ __forceinline__ ull fma2(ull a, ull b, ull c) {
    ull d; asm("fma.rn.f32x2 %0,%1,%2,%3;" : "=l"(d) : "l"(a), "l"(b), "l"(c)); return d;
}
__device__ __forceinline__ ull add2(ull a, ull b) {
    ull d; asm("add.rn.f32x2 %0,%1,%2;" : "=l"(d) : "l"(a), "l"(b)); return d;
}
__device__ __forceinline__ ull mul2(ull a, ull b) {
    ull d; asm("mul.rn.f32x2 %0,%1,%2;" : "=l"(d) : "l"(a), "l"(b)); return d;
}
__device__ __forceinline__ void unpk(ull v, float& lo, float& hi) {
    asm("mov.b64 {%0,%1}, %2;" : "=f"(lo), "=f"(hi) : "l"(v));
}
__device__ __forceinline__ ull pk2(float lo, float hi) {
    ull v; asm("mov.b64 %0, {%1,%2};" : "=l"(v) : "f"(lo), "f"(hi)); return v;
}
__device__ __forceinline__ ull pkc(float c) {
    unsigned u = __float_as_uint(c); return ((ull)u << 32) | (ull)u;
}
__device__ __forceinline__ float frcp(float x) {
    float r; asm("rcp.approx.f32 %0,%1;" : "=f"(r) : "f"(x)); return r;
}

// Exact-class GELU on a packed pair via A&S 7.1.28:
// erf(z) = 1 - (1 + a1 z + ... + a6 z^6)^-16, z>=0, |err|<=3e-7. No ex2, 2 rcp/pair.
// gelu(x) = 0.5x + 0.5|x|(1 - d^-16),  z = |x|/sqrt2,  0.5|x| = z/sqrt2.
__device__ __forceinline__ ull gelu2(ull s) {
    const ull C_ISQ2 = pkc(0.70710678118654752f);
    ull z = mul2(s & 0x7FFFFFFF7FFFFFFFULL, C_ISQ2);
    ull d = fma2(z, pkc(0.0000430638f), pkc(0.0002765672f));
    d = fma2(z, d, pkc(0.0001520143f));
    d = fma2(z, d, pkc(0.0092705272f));
    d = fma2(z, d, pkc(0.0422820123f));
    d = fma2(z, d, pkc(0.0705230784f));
    d = fma2(z, d, pkc(1.0f));
    d = mul2(d, d); d = mul2(d, d); d = mul2(d, d); d = mul2(d, d);   // d^16
    float dl, dh; unpk(d, dl, dh);
    ull r = pk2(frcp(dl), frcp(dh));                                  // d^-16
    ull u = mul2(z, C_ISQ2);                                          // 0.5|x|
    ull w = fma2(r ^ 0x8000000080000000ULL, u, u);                    // u(1-r)
    return fma2(s, pkc(0.5f), w);
}

// packed f32 pair -> (bf16x2 hi, bf16x2 lo-residual)
__device__ __forceinline__ void splitpair(ull v, unsigned& hb, unsigned& lb) {
    float f0, f1; unpk(v, f0, f1);
    unsigned h;
    asm("cvt.rn.bf16x2.f32 %0, %1, %2;" : "=r"(h) : "f"(f1), "f"(f0));
    float a0 = __uint_as_float(h << 16);
    float a1 = __uint_as_float(h & 0xFFFF0000u);
    float r0 = f0 - a0, r1 = f1 - a1;
    unsigned l;
    asm("cvt.rn.bf16x2.f32 %0, %1, %2;" : "=r"(l) : "f"(r1), "f"(r0));
    hb = h; lb = l;
}

// D += A(m16k16 bf16, row) @ B(k16n8 bf16, col); fp32 accum. Baseline PTX (sm_80+).
__device__ __forceinline__ void mma16816(float d[4], const unsigned a[4],
                                         unsigned b0, unsigned b1) {
    asm volatile(
        "mma.sync.aligned.m16n8k16.row.col.f32.bf16.bf16.f32 "
        "{%0,%1,%2,%3},{%4,%5,%6,%7},{%8,%9},{%0,%1,%2,%3};"
        : "+f"(d[0]), "+f"(d[1]), "+f"(d[2]), "+f"(d[3])
        : "r"(a[0]), "r"(a[1]), "r"(a[2]), "r"(a[3]), "r"(b0), "r"(b1));
}

// 16B unit(o,t,p): bytes[0,8)=hi frag {k=16t+2p,+1,+8,+9}, bytes[8,16)=lo frag.
// t XOR-swizzled -> 8-lane LDS.128 phases are bank-conflict-free.
template<int KT>
__device__ __forceinline__ int woff16(int o, int k) {
    int t = k >> 4, kk = k & 15, pp = (kk & 7) >> 1, half = kk >> 3;
    int ts = t ^ (o & (KT - 1));
    return ((o * KT + ts) * 4 + pp) * 16 + half * 4 + (k & 1) * 2;
}

// ---- one-shot fold kernel: BN-fold + bf16 hi/lo split into interleaved fragment layout ----
__global__ void fold_kernel(
    const float* __restrict__ W1, const float* __restrict__ g1, const float* __restrict__ b1,
    const float* __restrict__ m1, const float* __restrict__ v1,
    const float* __restrict__ W2, const float* __restrict__ g2, const float* __restrict__ b2,
    const float* __restrict__ m2, const float* __restrict__ v2,
    const float* __restrict__ W3, const float* __restrict__ g3, const float* __restrict__ b3,
    const float* __restrict__ m3, const float* __restrict__ v3)
{
    int i = blockIdx.x * blockDim.x + threadIdx.x;
    if (i < 2048) {                               // W1 [64x32]
        int o = i >> 5, k = i & 31;
        float w = W1[i] * (g1[o] * rsqrtf(v1[o] + EPS));
        __nv_bfloat16 hi = __float2bfloat16(w);
        int off = woff16<2>(o, k);
        *(__nv_bfloat16*)(wbuf + off)     = hi;
        *(__nv_bfloat16*)(wbuf + off + 8) = __float2bfloat16(w - __bfloat162float(hi));
    } else if (i < 2048 + 4096) {                 // W2 [64x64]
        int j = i - 2048, o = j >> 6, k = j & 63;
        float w = W2[j] * (g2[o] * rsqrtf(v2[o] + EPS));
        __nv_bfloat16 hi = __float2bfloat16(w);
        int off = 8192 + woff16<4>(o, k);
        *(__nv_bfloat16*)(wbuf + off)     = hi;
        *(__nv_bfloat16*)(wbuf + off + 8) = __float2bfloat16(w - __bfloat162float(hi));
    } else if (i < 2048 + 8192) {                 // W3 [64x64]
        int j = i - 6144, o = j >> 6, k = j & 63;
        float w = W3[j] * (g3[o] * rsqrtf(v3[o] + EPS));
        __nv_bfloat16 hi = __float2bfloat16(w);
        int off = 24576 + woff16<4>(o, k);
        *(__nv_bfloat16*)(wbuf + off)     = hi;
        *(__nv_bfloat16*)(wbuf + off + 8) = __float2bfloat16(w - __bfloat162float(hi));
    }
    if (i < 64) {
        bbuf[i]       = b1[i] - m1[i] * (g1[i] * rsqrtf(v1[i] + EPS));
        bbuf[64 + i]  = b2[i] - m2[i] * (g2[i] * rsqrtf(v2[i] + EPS));
        bbuf[128 + i] = b3[i] - m3[i] * (g3[i] * rsqrtf(v3[i] + EPS));
    }
}

// One GEMM stage (per warp, one 16-row m-tile): D[8][4] = (Ah+Al)@(Wh+Wl)^T, dropping lo*lo.
template<int KT>
__device__ __forceinline__ void run_stage(const char* w,
                                          unsigned Ah[4][4], unsigned Al[4][4],
                                          float D[8][4], int g, int p) {
    #pragma unroll
    for (int j = 0; j < 8; ++j)
        #pragma unroll
        for (int r = 0; r < 4; ++r) D[j][r] = 0.f;

    #pragma unroll
    for (int j = 0; j < 8; ++j) {
        int o = 8 * j + g;
        #pragma unroll
        for (int t = 0; t < KT; ++t) {
            int ts = t ^ (o & (KT - 1));
            int unit = (o * KT + ts) * 4 + p;
            ulonglong2 wv = *(const ulonglong2*)(w + unit * 16);   // one LDS.128: hi|lo
            unsigned bh0 = (unsigned)wv.x, bh1 = (unsigned)(wv.x >> 32);
            unsigned bl0 = (unsigned)wv.y, bl1 = (unsigned)(wv.y >> 32);
            mma16816(D[j], Ah[t], bh0, bh1);   // hi*hi
            mma16816(D[j], Ah[t], bl0, bl1);   // hi*lo
            mma16816(D[j], Al[t], bh0, bh1);   // lo*hi
        }
    }
}

// bias + gelu + re-split into next stage's A fragments (pure per-thread register work)
__device__ __forceinline__ void epilogue_mid(float D[8][4], const float* bias,
                                             unsigned Ah[4][4], unsigned Al[4][4], int p) {
    #pragma unroll
    for (int j = 0; j < 8; ++j) {
        ull bp = *(const ull*)(bias + 8 * j + 2 * p);
        int t = j >> 1;
        int rb = (j & 1) ? 2 : 0;
        ull v0 = gelu2(add2(pk2(D[j][0], D[j][1]), bp));
        ull v1 = gelu2(add2(pk2(D[j][2], D[j][3]), bp));
        splitpair(v0, Ah[t][rb],     Al[t][rb]);
        splitpair(v1, Ah[t][rb + 1], Al[t][rb + 1]);
    }
}

__global__ void __launch_bounds__(THREADS, 2) mlp_mma_kernel(
    const float* __restrict__ x, float* __restrict__ out)
{
    __shared__ __align__(16) float sbias[256];
    __shared__ __align__(16) char  sw[40960];
    const int tid = threadIdx.x;
    const int lane = tid & 31, wid = tid >> 5;   // warp = one 16-row m-tile
    const int g = lane >> 2, p = lane & 3;

    // ---- prologue: flat copy of pre-folded weights + biases into SMEM ----
    {
        const uint4* src = (const uint4*)wbuf;
        uint4* dst = (uint4*)sw;
        #pragma unroll
        for (int i = 0; i < 10; ++i) dst[tid + i * THREADS] = src[tid + i * THREADS];
        if (tid < 48) ((uint4*)sbias)[tid] = ((const uint4*)bbuf)[tid];
    }

    // ---- build stage-1 A fragments straight from GMEM (no staging) ----
    const int pbase = blockIdx.x * TILE_M;
    unsigned Ah[4][4], Al[4][4];
    {
        const float* xr = x + (size_t)(pbase + wid * 16 + g) * 32;   // row g; row g+8 = +256
        #pragma unroll
        for (int t = 0; t < 2; ++t) {
            int c0 = p * 2 + t * 16;
            splitpair(*(const ull*)(xr + c0),           Ah[t][0], Al[t][0]);
            splitpair(*(const ull*)(xr + 256 + c0),     Ah[t][1], Al[t][1]);
            splitpair(*(const ull*)(xr + c0 + 8),       Ah[t][2], Al[t][2]);
            splitpair(*(const ull*)(xr + 256 + c0 + 8), Ah[t][3], Al[t][3]);
        }
    }
    __syncthreads();

    float D[8][4];

    run_stage<2>(sw,         Ah, Al, D, g, p);
    epilogue_mid(D, sbias, Ah, Al, p);

    run_stage<4>(sw + 8192,  Ah, Al, D, g, p);
    epilogue_mid(D, sbias + 64, Ah, Al, p);

    run_stage<4>(sw + 24576, Ah, Al, D, g, p);

    // ---- final: bias + gelu -> direct transposed STG (4x32B segments per warp-instr) ----
    float* ob = out + (size_t)(pbase >> 10) * 65536 + (pbase & 1023) + wid * 16 + g;
    #pragma unroll
    for (int j = 0; j < 8; ++j) {
        ull bp = *(const ull*)(sbias + 128 + 8 * j + 2 * p);
        int o0 = 8 * j + 2 * p;
        ull v0 = gelu2(add2(pk2(D[j][0], D[j][1]), bp));   // cols o0,o0+1 @ row g
        ull v1 = gelu2(add2(pk2(D[j][2], D[j][3]), bp));   // cols o0,o0+1 @ row g+8
        float f0, f1;
        unpk(v0, f0, f1);
        ob[(size_t)o0 * 1024]       = f0;
        ob[(size_t)(o0 + 1) * 1024] = f1;
        unpk(v1, f0, f1);
        ob[(size_t)o0 * 1024 + 8]       = f0;
        ob[(size_t)(o0 + 1) * 1024 + 8] = f1;
    }
}

extern "C" void kernel_launch(void* const* d_in, const int* in_sizes, int n_in,
                              void* d_out, int out_size)
{
    const float* x  = (const float*)d_in[0];
    const float* W1 = (const float*)d_in[1];
    const float* g1 = (const float*)d_in[2];
    const float* b1 = (const float*)d_in[3];
    const float* m1 = (const float*)d_in[4];
    const float* v1 = (const float*)d_in[5];
    const float* W2 = (const float*)d_in[6];
    const float* g2 = (const float*)d_in[7];
    const float* b2 = (const float*)d_in[8];
    const float* m2 = (const float*)d_in[9];
    const float* v2 = (const float*)d_in[10];
    const float* W3 = (const float*)d_in[11];
    const float* g3 = (const float*)d_in[12];
    const float* b3 = (const float*)d_in[13];
    const float* m3 = (const float*)d_in[14];
    const float* v3 = (const float*)d_in[15];
    float* out = (float*)d_out;

    fold_kernel<<<40, 256>>>(W1, g1, b1, m1, v1, W2, g2, b2, m2, v2, W3, g3, b3, m3, v3);
    mlp_mma_kernel<<<NBLK, THREADS>>>(x, out);
}